// round 6
// baseline (speedup 1.0000x reference)
#include <cuda_runtime.h>

// S4D diagonal SSM: out[h,l] = 2*Re( sum_n cmod[h,n] * z[h,n]^l ),  z = exp(w*dt)
// Factor l = 64k + j (k in [0,32), j in [0,64)):
//   out[h,64k+j] = sum_n ( Bre[n,k]*Are[n,j] - Bim[n,k]*Aim[n,j] )
// Packing: A[n][j]=(ar,ai) float2, B[k][n]=(br,-bi) float2.
// fma.rn.f32x2 acc += B ⊗ A accumulates {Σ br*ar, Σ -bi*ai}; out = lo+hi.
// R6: 256 thr/block, 4k x 2j tile (16-reg acc) -> 32 warps/SM at 4 blocks/SM.

#define HDIM 1024
#define NDIM 64
#define LLEN 2048

#define AST 66                       // A row stride in float2 (64 + 2 pad)
#define BST 66                       // B row stride in float2 (528 B rows)
#define A_FLOATS (64*AST*2)          // 8448 floats (33792 B)
#define B_FLOATS (32*BST*2)          // 4224 floats (16896 B)
#define SMEM_FLOATS (A_FLOATS + B_FLOATS)   // 12672 floats = 50688 B

struct c2 { float re, im; };
__device__ __forceinline__ c2 cmul(c2 a, c2 b) {
    return { fmaf(a.re, b.re, -a.im*b.im), fmaf(a.re, b.im, a.im*b.re) };
}

__device__ __forceinline__ void fma2(unsigned long long& d,
                                     unsigned long long a,
                                     unsigned long long b) {
    asm("fma.rn.f32x2 %0, %1, %2, %0;" : "+l"(d) : "l"(a), "l"(b));
}

union U2 { unsigned long long u; float2 f; };

__global__ __launch_bounds__(256, 4) void ssk_diag_kernel(
    const float* __restrict__ log_dt,
    const float* __restrict__ log_w_real,
    const float* __restrict__ w_imag,
    const float* __restrict__ C_re,
    const float* __restrict__ C_im,
    float* __restrict__ out)
{
    extern __shared__ float sm[];
    float2* sA = reinterpret_cast<float2*>(sm);              // [64 n][AST]
    float2* sB = reinterpret_cast<float2*>(sm + A_FLOATS);   // [32 k][BST]

    const int h   = blockIdx.x;
    const int tid = threadIdx.x;

    // ------------- Phase 1: tables. tid = q*64 + n (4 threads per n) ---------------
    {
        const int n = tid & 63;
        const int q = tid >> 6;     // 0..3

        const float dtv = expf(log_dt[h]);
        const float wre = -expf(log_w_real[h*NDIM + n]);
        const float wim = w_imag[h*NDIM + n];
        const float are = wre * dtv;
        const float aim = wim * dtv;

        const float er = expf(are);
        float s, c; sincosf(aim, &s, &c);
        const c2 z = { er*c, er*s };

        // cmod = 2 * C * (z - 1) / w  (fold output factor 2)
        const float nre = z.re - 1.0f, nim = z.im;
        const float inv = 1.0f / (wre*wre + wim*wim);
        const float tre = (nre*wre + nim*wim) * inv;
        const float tim = (nim*wre - nre*wim) * inv;
        const float cr = C_re[h*NDIM + n], ci = C_im[h*NDIM + n];
        const c2 cm = { 2.0f*(cr*tre - ci*tim), 2.0f*(cr*tim + ci*tre) };

        // power ladder by squaring
        const c2 z2    = cmul(z,    z);
        const c2 z4    = cmul(z2,   z2);
        const c2 z8    = cmul(z4,   z4);
        const c2 z16   = cmul(z8,   z8);
        const c2 z32   = cmul(z16,  z16);
        const c2 z64   = cmul(z32,  z32);
        const c2 z128  = cmul(z64,  z64);
        const c2 z256  = cmul(z128, z128);
        const c2 z512  = cmul(z256, z256);
        const c2 z1024 = cmul(z512, z512);

        // A[n][j] = (re,im) of z^j, j = 16q .. 16q+15 ; start = z^(16q)
        c2 a = {1.0f, 0.0f};
        if (q & 1) a = z16;
        if (q & 2) a = cmul(a, z32);
        #pragma unroll
        for (int jj = 0; jj < 16; jj++) {
            sA[n*AST + 16*q + jj] = make_float2(a.re, a.im);
            a = cmul(a, z);
        }

        // B[k][n] = (re,-im) of cmod * z64^k, k = 8q .. 8q+7 ; start = cm * z^(512q)
        c2 b = cm;
        if (q & 1) b = cmul(b, z512);
        if (q & 2) b = cmul(b, z1024);
        #pragma unroll
        for (int kk = 0; kk < 8; kk++) {
            sB[(8*q + kk)*BST + n] = make_float2(b.re, -b.im);
            b = cmul(b, z64);
        }
    }
    __syncthreads();

    // ------------- Phase 2: contraction. tid = jp*8 + kq ---------------------------
    // Thread tile: k = kq + 8*kk (kk 0..3), j = 2*jp + jj (jj 0..1). 8 outputs.
    const int jp = tid >> 3;    // 0..31
    const int kq = tid & 7;     // 0..7

    const char* pA = reinterpret_cast<const char*>(sA) + (size_t)jp * 16;
    const char* pB = reinterpret_cast<const char*>(sB) + (size_t)kq * (BST*8);

    unsigned long long acc[4][2];   // [kk][jj]
    #pragma unroll
    for (int i = 0; i < 4; i++) { acc[i][0] = 0ull; acc[i][1] = 0ull; }

    #define LDA(off) (*reinterpret_cast<const ulonglong2*>(pA + (off)))
    #define LDB(off) (*reinterpret_cast<const ulonglong2*>(pB + (off)))

    #pragma unroll
    for (int n2 = 0; n2 < 32; n2++) {
        const int na = 2*n2, nb = 2*n2 + 1;
        // A for the 2-j tile: one 16B load per n
        const ulonglong2 aa = LDA((size_t)na*AST*8);   // .x = A[na][j0], .y = A[na][j0+1]
        const ulonglong2 ab = LDA((size_t)nb*AST*8);
        // B rows k = kq + 8*kk ; each 16B load covers (na, nb)
        const ulonglong2 b0 = LDB((size_t)na*8);
        const ulonglong2 b1 = LDB((size_t)BST*8*8  + na*8);
        const ulonglong2 b2 = LDB((size_t)BST*8*16 + na*8);
        const ulonglong2 b3 = LDB((size_t)BST*8*24 + na*8);

        fma2(acc[0][0], b0.x, aa.x);  fma2(acc[0][1], b0.x, aa.y);
        fma2(acc[1][0], b1.x, aa.x);  fma2(acc[1][1], b1.x, aa.y);
        fma2(acc[2][0], b2.x, aa.x);  fma2(acc[2][1], b2.x, aa.y);
        fma2(acc[3][0], b3.x, aa.x);  fma2(acc[3][1], b3.x, aa.y);

        fma2(acc[0][0], b0.y, ab.x);  fma2(acc[0][1], b0.y, ab.y);
        fma2(acc[1][0], b1.y, ab.x);  fma2(acc[1][1], b1.y, ab.y);
        fma2(acc[2][0], b2.y, ab.x);  fma2(acc[2][1], b2.y, ab.y);
        fma2(acc[3][0], b3.y, ab.x);  fma2(acc[3][1], b3.y, ab.y);
    }
    #undef LDA
    #undef LDB

    // Reduce packed halves; store: l = 64*(kq+8*kk) + 2*jp + jj  (float2 per kk)
    float* po = out + h*LLEN + kq*64 + jp*2;
    #pragma unroll
    for (int kk = 0; kk < 4; kk++) {
        float2 v;
        { U2 u; u.u = acc[kk][0]; v.x = u.f.x + u.f.y; }
        { U2 u; u.u = acc[kk][1]; v.y = u.f.x + u.f.y; }
        *reinterpret_cast<float2*>(po + kk*512) = v;
    }
}

extern "C" void kernel_launch(void* const* d_in, const int* in_sizes, int n_in,
                              void* d_out, int out_size)
{
    const float* log_dt     = (const float*)d_in[0];
    const float* log_w_real = (const float*)d_in[1];
    const float* w_imag     = (const float*)d_in[2];
    const float* C_re       = (const float*)d_in[3];
    const float* C_im       = (const float*)d_in[4];
    float* out = (float*)d_out;

    const int smem_bytes = SMEM_FLOATS * (int)sizeof(float);   // 50688 B
    cudaFuncSetAttribute(ssk_diag_kernel,
                         cudaFuncAttributeMaxDynamicSharedMemorySize, smem_bytes);

    ssk_diag_kernel<<<HDIM, 256, smem_bytes>>>(log_dt, log_w_real, w_imag,
                                               C_re, C_im, out);
}

// round 7
// speedup vs baseline: 1.3963x; 1.3963x over previous
#include <cuda_runtime.h>

// S4D diagonal SSM: out[h,l] = 2*Re( sum_n cmod[h,n] * z[h,n]^l ),  z = exp(w*dt)
// Factor l = 64k + j (k in [0,32), j in [0,64)):
//   out[h,64k+j] = sum_n ( Bre[n,k]*Are[n,j] - Bim[n,k]*Aim[n,j] )
// Packing: A[n][j]=(ar,ai) float2, B[k][n]=(br,-bi) float2.
// fma.rn.f32x2 acc += B ⊗ A accumulates {Σ br*ar, Σ -bi*ai}; out = lo+hi.
// R7: 64 thr/block, 8k x 4j tile per thread -> 0.1875 LDS.128 per FFMA2
//     (25% less L1 writeback traffic than R5's 4x4 tile).

#define HDIM 1024
#define NDIM 64
#define LLEN 2048

#define AST 66                       // A row stride in float2 (64 + 2 pad)
#define BST 66                       // B row stride in float2 (528 B rows)
#define A_FLOATS (64*AST*2)          // 8448 floats (33792 B)
#define B_FLOATS (32*BST*2)          // 4224 floats (16896 B)
#define SMEM_FLOATS (A_FLOATS + B_FLOATS)   // 12672 floats = 50688 B

struct c2 { float re, im; };
__device__ __forceinline__ c2 cmul(c2 a, c2 b) {
    return { fmaf(a.re, b.re, -a.im*b.im), fmaf(a.re, b.im, a.im*b.re) };
}

__device__ __forceinline__ void fma2(unsigned long long& d,
                                     unsigned long long a,
                                     unsigned long long b) {
    asm("fma.rn.f32x2 %0, %1, %2, %0;" : "+l"(d) : "l"(a), "l"(b));
}

union U2 { unsigned long long u; float2 f; };

__global__ __launch_bounds__(64, 4) void ssk_diag_kernel(
    const float* __restrict__ log_dt,
    const float* __restrict__ log_w_real,
    const float* __restrict__ w_imag,
    const float* __restrict__ C_re,
    const float* __restrict__ C_im,
    float* __restrict__ out)
{
    extern __shared__ float sm[];
    float2* sA = reinterpret_cast<float2*>(sm);              // [64 n][AST]
    float2* sB = reinterpret_cast<float2*>(sm + A_FLOATS);   // [32 k][BST]

    const int h   = blockIdx.x;
    const int tid = threadIdx.x;

    // ------------- Phase 1: tables. One n per thread, two interleaved chains --------
    {
        const int n = tid;   // 0..63

        const float dtv = expf(log_dt[h]);
        const float wre = -expf(log_w_real[h*NDIM + n]);
        const float wim = w_imag[h*NDIM + n];
        const float are = wre * dtv;
        const float aim = wim * dtv;

        const float er = expf(are);
        float s, c; sincosf(aim, &s, &c);
        const c2 z = { er*c, er*s };

        // cmod = 2 * C * (z - 1) / w  (fold output factor 2)
        const float nre = z.re - 1.0f, nim = z.im;
        const float inv = 1.0f / (wre*wre + wim*wim);
        const float tre = (nre*wre + nim*wim) * inv;
        const float tim = (nim*wre - nre*wim) * inv;
        const float cr = C_re[h*NDIM + n], ci = C_im[h*NDIM + n];
        const c2 cm = { 2.0f*(cr*tre - ci*tim), 2.0f*(cr*tim + ci*tre) };

        // power ladder by squaring
        const c2 z2    = cmul(z,    z);
        const c2 z4    = cmul(z2,   z2);
        const c2 z8    = cmul(z4,   z4);
        const c2 z16   = cmul(z8,   z8);
        const c2 z32   = cmul(z16,  z16);
        const c2 z64   = cmul(z32,  z32);
        const c2 z128  = cmul(z64,  z64);
        const c2 z256  = cmul(z128, z128);
        const c2 z512  = cmul(z256, z256);
        const c2 z1024 = cmul(z512, z512);

        // A[n][j]: two independent 32-long chains (ILP): j=0.. from 1, j=32.. from z32
        c2 a0 = {1.0f, 0.0f};
        c2 a1 = z32;
        #pragma unroll
        for (int jj = 0; jj < 32; jj++) {
            sA[n*AST + jj]      = make_float2(a0.re, a0.im);
            sA[n*AST + 32 + jj] = make_float2(a1.re, a1.im);
            a0 = cmul(a0, z);
            a1 = cmul(a1, z);
        }

        // B[k][n]: two independent 16-long chains: k=0.. from cm, k=16.. from cm*z1024
        c2 b0 = cm;
        c2 b1 = cmul(cm, z1024);
        #pragma unroll
        for (int kk = 0; kk < 16; kk++) {
            sB[kk*BST + n]        = make_float2(b0.re, -b0.im);
            sB[(16 + kk)*BST + n] = make_float2(b1.re, -b1.im);
            b0 = cmul(b0, z64);
            b1 = cmul(b1, z64);
        }
    }
    __syncthreads();

    // ------------- Phase 2: contraction. tid = jp*4 + kq ---------------------------
    // Thread tile: k = kq + 4*kk (kk 0..7), j = 4*jp + jj (jj 0..3). 32 outputs.
    const int jp = tid >> 2;    // 0..15
    const int kq = tid & 3;     // 0..3

    const char* pA = reinterpret_cast<const char*>(sA) + (size_t)jp * 32;
    const char* pB = reinterpret_cast<const char*>(sB) + (size_t)kq * (BST*8);

    unsigned long long acc[8][4];   // [kk][jj]
    #pragma unroll
    for (int i = 0; i < 8; i++)
        #pragma unroll
        for (int jj = 0; jj < 4; jj++) acc[i][jj] = 0ull;

    #define LDA(off) (*reinterpret_cast<const ulonglong2*>(pA + (off)))
    #define LDB(off) (*reinterpret_cast<const ulonglong2*>(pB + (off)))

    #pragma unroll 8
    for (int n2 = 0; n2 < 32; n2++) {
        const int na = 2*n2, nb = 2*n2 + 1;
        // A: 16B per n covers 2 j-pairs; 8 jp lanes -> full 128B wavefronts
        const ulonglong2 aa0 = LDA((size_t)na*AST*8);
        const ulonglong2 aa1 = LDA((size_t)na*AST*8 + 16);
        const ulonglong2 ab0 = LDA((size_t)nb*AST*8);
        const ulonglong2 ab1 = LDA((size_t)nb*AST*8 + 16);
        // B: rows k = kq + 4*kk; each 16B covers (na, nb)
        ulonglong2 b[8];
        #pragma unroll
        for (int kk = 0; kk < 8; kk++)
            b[kk] = LDB((size_t)kk*(4*BST*8) + (size_t)na*8);

        #pragma unroll
        for (int kk = 0; kk < 8; kk++) {
            fma2(acc[kk][0], b[kk].x, aa0.x);
            fma2(acc[kk][1], b[kk].x, aa0.y);
            fma2(acc[kk][2], b[kk].x, aa1.x);
            fma2(acc[kk][3], b[kk].x, aa1.y);
            fma2(acc[kk][0], b[kk].y, ab0.x);
            fma2(acc[kk][1], b[kk].y, ab0.y);
            fma2(acc[kk][2], b[kk].y, ab1.x);
            fma2(acc[kk][3], b[kk].y, ab1.y);
        }
    }
    #undef LDA
    #undef LDB

    // Reduce packed halves; store: l = 64*(kq+4*kk) + 4*jp + jj  (float4 per kk)
    float* po = out + h*LLEN + kq*64 + jp*4;
    #pragma unroll
    for (int kk = 0; kk < 8; kk++) {
        float4 v;
        { U2 u; u.u = acc[kk][0]; v.x = u.f.x + u.f.y; }
        { U2 u; u.u = acc[kk][1]; v.y = u.f.x + u.f.y; }
        { U2 u; u.u = acc[kk][2]; v.z = u.f.x + u.f.y; }
        { U2 u; u.u = acc[kk][3]; v.w = u.f.x + u.f.y; }
        *reinterpret_cast<float4*>(po + kk*256) = v;
    }
}

extern "C" void kernel_launch(void* const* d_in, const int* in_sizes, int n_in,
                              void* d_out, int out_size)
{
    const float* log_dt     = (const float*)d_in[0];
    const float* log_w_real = (const float*)d_in[1];
    const float* w_imag     = (const float*)d_in[2];
    const float* C_re       = (const float*)d_in[3];
    const float* C_im       = (const float*)d_in[4];
    float* out = (float*)d_out;

    const int smem_bytes = SMEM_FLOATS * (int)sizeof(float);   // 50688 B
    cudaFuncSetAttribute(ssk_diag_kernel,
                         cudaFuncAttributeMaxDynamicSharedMemorySize, smem_bytes);

    ssk_diag_kernel<<<HDIM, 64, smem_bytes>>>(log_dt, log_w_real, w_imag,
                                              C_re, C_im, out);
}